// round 16
// baseline (speedup 1.0000x reference)
#include <cuda_runtime.h>
#include <cstdint>

#define NN 50000
#define NE 600000
#define NG 64

// ---------------- scratch (no allocations allowed; self-restoring state) ----------------
__device__ __align__(16) float g_agg[(size_t)NN * 128];
__device__ __align__(16) float g_h  [(size_t)NN * 128];
__device__ __align__(16) float g_pool[NG * 128];   // zeroed by finalize after use
__device__ __align__(16) float g_cnt[NG];          // zeroed by finalize after use
// CSR scratch
__device__ __align__(16) int g_cntE[NN];           // zeroed by scan1 after use
__device__ int    g_rowptr[NN + 1];
__device__ int    g_wofs[NN];
__device__ float4 g_erec[NE];      // {src(bitcast), a0, a1, a2} per dst-sorted slot
__device__ int    g_bsum[128];

// ---------------- helpers ----------------
__device__ __forceinline__ void red_add_v4(float* addr, float a, float b, float c, float d) {
    asm volatile("red.global.add.v4.f32 [%0], {%1,%2,%3,%4};"
                 :: "l"(addr), "f"(a), "f"(b), "f"(c), "f"(d) : "memory");
}
__device__ __forceinline__ long long load_idx(const void* p, long long i, int is64) {
    if (is64) return ((const long long*)p)[i];
    return (long long)((const int*)p)[i];
}
__device__ __forceinline__ uint32_t f2tf32(float x) {
    uint32_t r;
    asm("cvt.rna.tf32.f32 %0, %1;" : "=r"(r) : "f"(x));
    return r;
}
__device__ __forceinline__ void mma16n8k8(float* c, const uint32_t* a, uint32_t b0, uint32_t b1) {
    asm volatile("mma.sync.aligned.m16n8k8.row.col.f32.tf32.tf32.f32 "
                 "{%0,%1,%2,%3}, {%4,%5,%6,%7}, {%8,%9}, {%0,%1,%2,%3};"
                 : "+f"(c[0]), "+f"(c[1]), "+f"(c[2]), "+f"(c[3])
                 : "r"(a[0]), "r"(a[1]), "r"(a[2]), "r"(a[3]), "r"(b0), "r"(b1));
}

// inline int64-vs-int32 detection. ONLY sound on edge_index (random node ids);
// NEVER on sorted `batch` (leading zeros misdetect as int64 — round-11 bug).
__device__ __forceinline__ int detect_is64(const int* ei32, int tid) {
    __shared__ int s_is64;
    if (tid < 32) {
        int v = ei32[2 * tid + 1] | ei32[2 * (tid + 32) + 1];
        unsigned bl = __ballot_sync(0xffffffffu, v != 0);
        if (tid == 0) s_is64 = (bl == 0) ? 1 : 0;
    }
    __syncthreads();
    return s_is64;
}

// ---------------- CSR build (dst-binned) ----------------
__global__ void hist_kernel(const void* __restrict__ ei, int* __restrict__ cnt) {
    int is64 = detect_is64((const int*)ei, threadIdx.x);
    int e = blockIdx.x * blockDim.x + threadIdx.x;   // 32-bit: NE < 2^31
    if (e < NE) {
        int dst = (int)load_idx(ei, (long long)NE + e, is64);
        atomicAdd(&cnt[dst], 1);
    }
}
// block-local exclusive scan of counts; consumes + zeroes cntE (self-restore)
__global__ void scan1_kernel(int* __restrict__ cnt, int* __restrict__ rowptr,
                             int* __restrict__ bsum) {
    __shared__ int wsum[16];
    int tid = threadIdx.x, lane = tid & 31, wid = tid >> 5;
    int i = blockIdx.x * 512 + tid;
    int v = 0;
    if (i < NN) { v = cnt[i]; cnt[i] = 0; }   // read + restore for next replay
    int s = v;
#pragma unroll
    for (int ofs = 1; ofs < 32; ofs <<= 1) {
        int t = __shfl_up_sync(0xffffffffu, s, ofs);
        if (lane >= ofs) s += t;
    }
    if (lane == 31) wsum[wid] = s;
    __syncthreads();
    if (wid == 0 && lane < 16) {
        int w = wsum[lane];
        int ws = w;
#pragma unroll
        for (int ofs = 1; ofs < 16; ofs <<= 1) {
            int t = __shfl_up_sync(0xffffu, ws, ofs);
            if (lane >= ofs) ws += t;
        }
        wsum[lane] = ws - w;
    }
    __syncthreads();
    int incl = s + wsum[wid];
    if (i < NN) rowptr[i] = incl - v;
    if (tid == 511) bsum[blockIdx.x] = incl;
}
// adds predecessor-block sum (computed in-kernel from bsum; replaces scan2)
__global__ void scan3_kernel(int* __restrict__ rowptr, const int* __restrict__ bsum,
                             int* __restrict__ wofs) {
    __shared__ int bpre_s;
    int tid = threadIdx.x, lane = tid & 31, wid = tid >> 5;
    int b = blockIdx.x;            // 512-node blocks, matching scan1
    if (wid == 0) {
        int sum = 0;
        for (int j = lane; j < b; j += 32) sum += __ldg(&bsum[j]);
#pragma unroll
        for (int o = 16; o; o >>= 1) sum += __shfl_down_sync(0xffffffffu, sum, o);
        if (lane == 0) bpre_s = sum;
    }
    __syncthreads();
    int i = b * 512 + tid;
    if (i < NN) {
        int r = rowptr[i] + bpre_s;
        rowptr[i] = r;
        wofs[i] = r;
    }
    if (i == 0) rowptr[NN] = NE;
}
__global__ void scatter_kernel(const void* __restrict__ ei, const float* __restrict__ attr,
                               int* __restrict__ wofs, float4* __restrict__ rec) {
    int is64 = detect_is64((const int*)ei, threadIdx.x);
    int e = blockIdx.x * blockDim.x + threadIdx.x;   // 32-bit
    if (e < NE) {
        int dst = (int)load_idx(ei, (long long)NE + e, is64);
        int src = (int)load_idx(ei, e, is64);
        int pos = atomicAdd(&wofs[dst], 1);
        float4 r;
        r.x = __int_as_float(src);
        r.y = __ldg(&attr[e * 3 + 0]);
        r.z = __ldg(&attr[e * 3 + 1]);
        r.w = __ldg(&attr[e * 3 + 2]);
        rec[pos] = r;
    }
}

// ---------------- gather aggregation (round-13 optimum: VPL=2, unchanged) ----------------
template <int CH, int SPLIT>
__global__ void agg_kernel(const float* __restrict__ x, const float4* __restrict__ recs,
                           const float* __restrict__ ew, const float* __restrict__ eb,
                           const int* __restrict__ rowptr, float* __restrict__ out) {
    const int VPL = CH / (32 * SPLIT);   // = 2 for both instantiations
    int gw = (int)(((long long)blockIdx.x * blockDim.x + threadIdx.x) >> 5);
    int lane = threadIdx.x & 31;
    if (gw >= NN * SPLIT) return;
    int node = (SPLIT == 2) ? (gw >> 1) : gw;
    int half = (SPLIT == 2) ? (gw & 1) : 0;
    int c0 = (half * 32 + lane) * VPL;

    float ew0[VPL], ew1[VPL], ew2[VPL], ebv[VPL], acc[VPL];
#pragma unroll
    for (int j = 0; j < VPL; j++) {
        ew0[j] = __ldg(&ew[c0 + j]);
        ew1[j] = __ldg(&ew[CH + c0 + j]);
        ew2[j] = __ldg(&ew[2 * CH + c0 + j]);
        ebv[j] = __ldg(&eb[c0 + j]);
        acc[j] = 0.f;
    }
    int beg = __ldg(&rowptr[node]);
    int end = __ldg(&rowptr[node + 1]);
    int p = beg;
    for (; p + 3 < end; p += 4) {
        float4 r[4];
        float xv[4][VPL];
#pragma unroll
        for (int u = 0; u < 4; u++) r[u] = __ldg(&recs[p + u]);
#pragma unroll
        for (int u = 0; u < 4; u++) {
            int xoff = __float_as_int(r[u].x) * CH + c0;   // 32-bit index math
            *(float2*)xv[u] = *(const float2*)&x[xoff];
        }
#pragma unroll
        for (int u = 0; u < 4; u++)
#pragma unroll
            for (int j = 0; j < VPL; j++) {
                float ev = ebv[j] + r[u].y * ew0[j] + r[u].z * ew1[j] + r[u].w * ew2[j];
                acc[j] += fmaxf(xv[u][j] + ev, 0.f);
            }
    }
    for (; p < end; p++) {
        float4 r0 = __ldg(&recs[p]);
        int xoff = __float_as_int(r0.x) * CH + c0;
        float x0[VPL];
        *(float2*)x0 = *(const float2*)&x[xoff];
#pragma unroll
        for (int j = 0; j < VPL; j++) {
            float e0 = ebv[j] + r0.y * ew0[j] + r0.z * ew1[j] + r0.w * ew2[j];
            acc[j] += fmaxf(x0[j] + e0, 0.f);
        }
    }
    int soff = node * CH + c0;
    float sv[VPL];
    *(float2*)sv = *(const float2*)&x[soff];
#pragma unroll
    for (int j = 0; j < VPL; j++) sv[j] += acc[j];
    *(float2*)&out[soff] = *(float2*)sv;
}

// ---------------- fused 2-GEMM node MLP (unchanged, proven) ----------------
template <int K1>
__global__ __launch_bounds__(256, 2) void fused_mlp_kernel(
    const float* __restrict__ A, const float* __restrict__ W1, const float* __restrict__ b1,
    const float* __restrict__ W2, const float* __restrict__ b2, float* __restrict__ C) {
    extern __shared__ uint32_t sm[];
    uint32_t (*As)[20]   = (uint32_t(*)[20])sm;
    uint32_t (*Ws)[136]  = (uint32_t(*)[136])(sm + 128 * 20);
    uint32_t (*Mid)[132] = (uint32_t(*)[132])(sm + 128 * 20 + 16 * 136);

    const int tid = threadIdx.x, lane = tid & 31, wid = tid >> 5;
    const int block_row = blockIdx.x * 128;
    const int rbase = (wid & 3) * 32;
    const int cbase = (wid >> 2) * 64;
    const int g4 = lane >> 2;
    const int t4 = lane & 3;

    float acc[2][8][4];
#pragma unroll
    for (int i = 0; i < 2; i++)
#pragma unroll
        for (int j = 0; j < 8; j++)
#pragma unroll
            for (int q = 0; q < 4; q++) acc[i][j][q] = 0.f;

    for (int k0 = 0; k0 < K1; k0 += 16) {
#pragma unroll
        for (int i = 0; i < 2; i++) {
            int idx = tid + i * 256;
            int r = idx >> 2;
            int kc = (idx & 3) * 4;
            int gr = block_row + r;
            float4 v = make_float4(0.f, 0.f, 0.f, 0.f);
            if (gr < NN) v = *(const float4*)&A[(long long)gr * K1 + k0 + kc];
            *(uint4*)&As[r][kc] = make_uint4(f2tf32(v.x), f2tf32(v.y), f2tf32(v.z), f2tf32(v.w));
        }
#pragma unroll
        for (int i = 0; i < 2; i++) {
            int idx = tid + i * 256;
            int r = idx >> 5;
            int cc = (idx & 31) * 4;
            float4 v = *(const float4*)&W1[(long long)(k0 + r) * 128 + cc];
            *(uint4*)&Ws[r][cc] = make_uint4(f2tf32(v.x), f2tf32(v.y), f2tf32(v.z), f2tf32(v.w));
        }
        __syncthreads();
#pragma unroll
        for (int ks = 0; ks < 2; ks++) {
            const int kk = ks * 8;
            uint32_t a[2][4];
#pragma unroll
            for (int i = 0; i < 2; i++) {
                int r = rbase + i * 16 + g4;
                a[i][0] = As[r][kk + t4];
                a[i][1] = As[r + 8][kk + t4];
                a[i][2] = As[r][kk + t4 + 4];
                a[i][3] = As[r + 8][kk + t4 + 4];
            }
#pragma unroll
            for (int j = 0; j < 8; j++) {
                int cn = cbase + j * 8 + g4;
                uint32_t b0 = Ws[kk + t4][cn];
                uint32_t b1 = Ws[kk + t4 + 4][cn];
#pragma unroll
                for (int i = 0; i < 2; i++) mma16n8k8(acc[i][j], a[i], b0, b1);
            }
        }
        __syncthreads();
    }
#pragma unroll
    for (int j = 0; j < 8; j++) {
        int col = cbase + j * 8 + t4 * 2;
        float bx = __ldg(&b1[col]);
        float by = __ldg(&b1[col + 1]);
#pragma unroll
        for (int i = 0; i < 2; i++) {
            int r0 = rbase + i * 16 + g4;
            Mid[r0][col]         = f2tf32(fmaxf(acc[i][j][0] + bx, 0.f));
            Mid[r0][col + 1]     = f2tf32(fmaxf(acc[i][j][1] + by, 0.f));
            Mid[r0 + 8][col]     = f2tf32(fmaxf(acc[i][j][2] + bx, 0.f));
            Mid[r0 + 8][col + 1] = f2tf32(fmaxf(acc[i][j][3] + by, 0.f));
            acc[i][j][0] = 0.f; acc[i][j][1] = 0.f; acc[i][j][2] = 0.f; acc[i][j][3] = 0.f;
        }
    }
    __syncthreads();

    for (int k0 = 0; k0 < 128; k0 += 16) {
#pragma unroll
        for (int i = 0; i < 2; i++) {
            int idx = tid + i * 256;
            int r = idx >> 5;
            int cc = (idx & 31) * 4;
            float4 v = *(const float4*)&W2[(long long)(k0 + r) * 128 + cc];
            *(uint4*)&Ws[r][cc] = make_uint4(f2tf32(v.x), f2tf32(v.y), f2tf32(v.z), f2tf32(v.w));
        }
        __syncthreads();
#pragma unroll
        for (int ks = 0; ks < 2; ks++) {
            const int kk = ks * 8;
            uint32_t a[2][4];
#pragma unroll
            for (int i = 0; i < 2; i++) {
                int r = rbase + i * 16 + g4;
                a[i][0] = Mid[r][k0 + kk + t4];
                a[i][1] = Mid[r + 8][k0 + kk + t4];
                a[i][2] = Mid[r][k0 + kk + t4 + 4];
                a[i][3] = Mid[r + 8][k0 + kk + t4 + 4];
            }
#pragma unroll
            for (int j = 0; j < 8; j++) {
                int cn = cbase + j * 8 + g4;
                uint32_t b0 = Ws[kk + t4][cn];
                uint32_t b1 = Ws[kk + t4 + 4][cn];
#pragma unroll
                for (int i = 0; i < 2; i++) mma16n8k8(acc[i][j], a[i], b0, b1);
            }
        }
        __syncthreads();
    }
#pragma unroll
    for (int j = 0; j < 8; j++) {
        int col = cbase + j * 8 + t4 * 2;
        float bx = __ldg(&b2[col]);
        float by = __ldg(&b2[col + 1]);
#pragma unroll
        for (int i = 0; i < 2; i++) {
            int r0 = block_row + rbase + i * 16 + g4;
            if (r0 < NN) {
                float2 o0 = make_float2(fmaxf(acc[i][j][0] + bx, 0.f),
                                        fmaxf(acc[i][j][1] + by, 0.f));
                *(float2*)&C[(long long)r0 * 128 + col] = o0;
            }
            if (r0 + 8 < NN) {
                float2 o1 = make_float2(fmaxf(acc[i][j][2] + bx, 0.f),
                                        fmaxf(acc[i][j][3] + by, 0.f));
                *(float2*)&C[(long long)(r0 + 8) * 128 + col] = o1;
            }
        }
    }
}

// ---------------- global mean pool ----------------
__global__ void pool_kernel(const float* __restrict__ h, const void* __restrict__ batch,
                            const void* __restrict__ ei,
                            float* __restrict__ pool, float* __restrict__ cnt) {
    int is64 = detect_is64((const int*)ei, threadIdx.x);  // width from ei; batch shares dtype
    int idx = blockIdx.x * blockDim.x + threadIdx.x;      // 32-bit: NN*32 = 1.6M
    if (idx >= NN * 32) return;
    int n = idx >> 5;
    int c4 = (idx & 31) * 4;
    int g = (int)load_idx(batch, n, is64);
    float4 v = *(const float4*)&h[n * 128 + c4];
    red_add_v4(&pool[g * 128 + c4], v.x, v.y, v.z, v.w);
    if (c4 == 0) atomicAdd(&cnt[g], 1.0f);
}
// single block: read all, then self-restore pool/cnt (no cross-block race)
__global__ void finalize_kernel(float* __restrict__ pool, float* __restrict__ cnt,
                                float* __restrict__ out) {
    int tid = threadIdx.x;
    for (int i = tid; i < NG * 128; i += 1024) {
        out[i] = pool[i] / fmaxf(cnt[i >> 7], 1.0f);
        pool[i] = 0.f;
    }
    __syncthreads();
    if (tid < NG) cnt[tid] = 0.f;
}

// ---------------- launch ----------------
extern "C" void kernel_launch(void* const* d_in, const int* in_sizes, int n_in,
                              void* d_out, int out_size) {
    const float* x     = (const float*)d_in[0];
    const void*  ei    = d_in[1];
    const float* attr  = (const float*)d_in[2];
    const void*  batch = d_in[3];
    const float* el1_w = (const float*)d_in[4];
    const float* el1_b = (const float*)d_in[5];
    const float* w1a   = (const float*)d_in[6];
    const float* b1a   = (const float*)d_in[7];
    const float* w1b   = (const float*)d_in[8];
    const float* b1b   = (const float*)d_in[9];
    const float* el2_w = (const float*)d_in[10];
    const float* el2_b = (const float*)d_in[11];
    const float* w2a   = (const float*)d_in[12];
    const float* b2a   = (const float*)d_in[13];
    const float* w2b   = (const float*)d_in[14];
    const float* b2b   = (const float*)d_in[15];
    float* out = (float*)d_out;

    float *agg, *h, *pool, *cnt;
    int *cntE, *rowptr, *wofs, *bsum;
    float4* erec;
    cudaGetSymbolAddress((void**)&agg,  g_agg);
    cudaGetSymbolAddress((void**)&h,    g_h);
    cudaGetSymbolAddress((void**)&pool, g_pool);
    cudaGetSymbolAddress((void**)&cnt,  g_cnt);
    cudaGetSymbolAddress((void**)&cntE,   g_cntE);
    cudaGetSymbolAddress((void**)&rowptr, g_rowptr);
    cudaGetSymbolAddress((void**)&wofs,   g_wofs);
    cudaGetSymbolAddress((void**)&erec,   g_erec);
    cudaGetSymbolAddress((void**)&bsum,   g_bsum);

    const int SMF = (128 * 20 + 16 * 136 + 128 * 132) * 4;   // 86528 B
    cudaFuncSetAttribute(fused_mlp_kernel<64>,  cudaFuncAttributeMaxDynamicSharedMemorySize, SMF);
    cudaFuncSetAttribute(fused_mlp_kernel<128>, cudaFuncAttributeMaxDynamicSharedMemorySize, SMF);

    const int NB = (NN + 511) / 512;   // 98

    // 1-4: CSR build (self-restoring cntE; scan2 folded into scan3)
    hist_kernel<<<(NE + 255) / 256, 256>>>(ei, cntE);
    scan1_kernel<<<NB, 512>>>(cntE, rowptr, bsum);
    scan3_kernel<<<NB, 512>>>(rowptr, bsum, wofs);
    scatter_kernel<<<(NE + 255) / 256, 256>>>(ei, attr, wofs, erec);

    const int ggrid = (NN + 127) / 128;

    // 5-6: layer 1 (SPLIT=1: 50k warps, VPL=2)
    {
        long long t = (long long)NN * 32;
        agg_kernel<64, 1><<<(int)((t + 255) / 256), 256>>>(x, erec, el1_w, el1_b, rowptr, agg);
    }
    fused_mlp_kernel<64><<<ggrid, 256, SMF>>>(agg, w1a, b1a, w1b, b1b, h);

    // 7-8: layer 2 (SPLIT=2: 100k half-warps, VPL=2)
    {
        long long t = (long long)NN * 64;
        agg_kernel<128, 2><<<(int)((t + 255) / 256), 256>>>(h, erec, el2_w, el2_b, rowptr, agg);
    }
    fused_mlp_kernel<128><<<ggrid, 256, SMF>>>(agg, w2a, b2a, w2b, b2b, h);

    // 9-10: pool + finalize (finalize self-restores pool/cnt)
    {
        long long t = (long long)NN * 32;
        pool_kernel<<<(int)((t + 255) / 256), 256>>>(h, batch, ei, pool, cnt);
    }
    finalize_kernel<<<1, 1024>>>(pool, cnt, out);
}

// round 17
// speedup vs baseline: 1.0115x; 1.0115x over previous
#include <cuda_runtime.h>
#include <cstdint>

#define NN 50000
#define NE 600000
#define NG 64

// ---------------- scratch (no allocations allowed) ----------------
__device__ __align__(16) float g_agg[(size_t)NN * 128];
__device__ __align__(16) float g_h  [(size_t)NN * 128];
__device__ __align__(16) float g_pool[NG * 128];
__device__ __align__(16) float g_cnt[NG];
__device__ int   g_is64;
// CSR scratch
__device__ __align__(16) int g_cntE[NN];
__device__ int    g_rowptr[NN + 1];
__device__ int    g_wofs[NN];
__device__ float4 g_erec[NE];      // {src(bitcast), a0, a1, a2} per dst-sorted slot
__device__ int    g_bsum[128];

// ---------------- helpers ----------------
__device__ __forceinline__ void red_add_v4(float* addr, float a, float b, float c, float d) {
    asm volatile("red.global.add.v4.f32 [%0], {%1,%2,%3,%4};"
                 :: "l"(addr), "f"(a), "f"(b), "f"(c), "f"(d) : "memory");
}
__device__ __forceinline__ long long load_idx(const void* p, long long i, int is64) {
    if (is64) return ((const long long*)p)[i];
    return (long long)((const int*)p)[i];
}
__device__ __forceinline__ uint32_t f2tf32(float x) {
    uint32_t r;
    asm("cvt.rna.tf32.f32 %0, %1;" : "=r"(r) : "f"(x));
    return r;
}
__device__ __forceinline__ void mma16n8k8(float* c, const uint32_t* a, uint32_t b0, uint32_t b1) {
    asm volatile("mma.sync.aligned.m16n8k8.row.col.f32.tf32.tf32.f32 "
                 "{%0,%1,%2,%3}, {%4,%5,%6,%7}, {%8,%9}, {%0,%1,%2,%3};"
                 : "+f"(c[0]), "+f"(c[1]), "+f"(c[2]), "+f"(c[3])
                 : "r"(a[0]), "r"(a[1]), "r"(a[2]), "r"(a[3]), "r"(b0), "r"(b1));
}

// ---------------- init: detect + ALL zeroing in one launch ----------------
__global__ void init_kernel(const int* __restrict__ ei32) {
    int b = blockIdx.x, tid = threadIdx.x;
    if (b == 0) {
        if (tid < 32) {
            int v = ei32[2 * tid + 1] | ei32[2 * (tid + 32) + 1];
            unsigned bl = __ballot_sync(0xffffffffu, v != 0);
            if (tid == 0) g_is64 = (bl == 0) ? 1 : 0;
        } else if (tid >= 64 && tid < 128) {
            g_cnt[tid - 64] = 0.f;
        }
        return;
    }
    if (b <= 50) {
        int i = (b - 1) * 256 + tid;
        if (i < 12500) ((float4*)g_cntE)[i] = make_float4(0.f, 0.f, 0.f, 0.f);
        return;
    }
    int i = (b - 51) * 256 + tid;
    ((float4*)g_pool)[i] = make_float4(0.f, 0.f, 0.f, 0.f);
}

// ---------------- CSR build (dst-binned) ----------------
__global__ void hist_kernel(const void* __restrict__ ei, int* __restrict__ cnt) {
    int e = blockIdx.x * blockDim.x + threadIdx.x;   // 32-bit: NE < 2^31
    if (e < NE) {
        int dst = (int)load_idx(ei, (long long)NE + e, g_is64);
        atomicAdd(&cnt[dst], 1);
    }
}
__global__ void scan1_kernel(const int* __restrict__ cnt, int* __restrict__ rowptr,
                             int* __restrict__ bsum) {
    __shared__ int wsum[16];
    int tid = threadIdx.x, lane = tid & 31, wid = tid >> 5;
    int i = blockIdx.x * 512 + tid;
    int v = (i < NN) ? cnt[i] : 0;
    int s = v;
#pragma unroll
    for (int ofs = 1; ofs < 32; ofs <<= 1) {
        int t = __shfl_up_sync(0xffffffffu, s, ofs);
        if (lane >= ofs) s += t;
    }
    if (lane == 31) wsum[wid] = s;
    __syncthreads();
    if (wid == 0 && lane < 16) {
        int w = wsum[lane];
        int ws = w;
#pragma unroll
        for (int ofs = 1; ofs < 16; ofs <<= 1) {
            int t = __shfl_up_sync(0xffffu, ws, ofs);
            if (lane >= ofs) ws += t;
        }
        wsum[lane] = ws - w;
    }
    __syncthreads();
    int incl = s + wsum[wid];
    if (i < NN) rowptr[i] = incl - v;
    if (tid == 511) bsum[blockIdx.x] = incl;
}
// scan2 folded in: warp 0 sums predecessor block aggregates directly (<= 97 loads)
__global__ void scan3_kernel(int* __restrict__ rowptr, const int* __restrict__ bsum,
                             int* __restrict__ wofs) {
    __shared__ int bpre_s;
    int tid = threadIdx.x, lane = tid & 31, wid = tid >> 5;
    int b = blockIdx.x;            // 512-node blocks, matching scan1
    if (wid == 0) {
        int sum = 0;
        for (int j = lane; j < b; j += 32) sum += __ldg(&bsum[j]);
#pragma unroll
        for (int o = 16; o; o >>= 1) sum += __shfl_down_sync(0xffffffffu, sum, o);
        if (lane == 0) bpre_s = sum;
    }
    __syncthreads();
    int i = b * 512 + tid;
    if (i < NN) {
        int r = rowptr[i] + bpre_s;
        rowptr[i] = r;
        wofs[i] = r;
    }
    if (i == 0) rowptr[NN] = NE;
}
__global__ void scatter_kernel(const void* __restrict__ ei, const float* __restrict__ attr,
                               int* __restrict__ wofs, float4* __restrict__ rec) {
    int e = blockIdx.x * blockDim.x + threadIdx.x;   // 32-bit: NE < 2^31
    if (e < NE) {
        int is64 = g_is64;
        int dst = (int)load_idx(ei, (long long)NE + e, is64);
        int src = (int)load_idx(ei, e, is64);
        int pos = atomicAdd(&wofs[dst], 1);
        float4 r;
        r.x = __int_as_float(src);
        r.y = __ldg(&attr[e * 3 + 0]);
        r.z = __ldg(&attr[e * 3 + 1]);
        r.w = __ldg(&attr[e * 3 + 2]);
        rec[pos] = r;
    }
}

// ---------------- gather aggregation (round-13 optimum: VPL=2 everywhere) ----------------
template <int CH, int SPLIT>
__global__ void agg_kernel(const float* __restrict__ x, const float4* __restrict__ recs,
                           const float* __restrict__ ew, const float* __restrict__ eb,
                           const int* __restrict__ rowptr, float* __restrict__ out) {
    const int VPL = CH / (32 * SPLIT);   // = 2 for both instantiations
    int gw = (int)(((long long)blockIdx.x * blockDim.x + threadIdx.x) >> 5);
    int lane = threadIdx.x & 31;
    if (gw >= NN * SPLIT) return;
    int node = (SPLIT == 2) ? (gw >> 1) : gw;
    int half = (SPLIT == 2) ? (gw & 1) : 0;
    int c0 = (half * 32 + lane) * VPL;

    float ew0[VPL], ew1[VPL], ew2[VPL], ebv[VPL], acc[VPL];
#pragma unroll
    for (int j = 0; j < VPL; j++) {
        ew0[j] = __ldg(&ew[c0 + j]);
        ew1[j] = __ldg(&ew[CH + c0 + j]);
        ew2[j] = __ldg(&ew[2 * CH + c0 + j]);
        ebv[j] = __ldg(&eb[c0 + j]);
        acc[j] = 0.f;
    }
    int beg = __ldg(&rowptr[node]);
    int end = __ldg(&rowptr[node + 1]);
    int p = beg;
    for (; p + 3 < end; p += 4) {
        float4 r[4];
        float xv[4][VPL];
#pragma unroll
        for (int u = 0; u < 4; u++) r[u] = __ldg(&recs[p + u]);
#pragma unroll
        for (int u = 0; u < 4; u++) {
            int xoff = __float_as_int(r[u].x) * CH + c0;   // 32-bit index math
            *(float2*)xv[u] = *(const float2*)&x[xoff];
        }
#pragma unroll
        for (int u = 0; u < 4; u++)
#pragma unroll
            for (int j = 0; j < VPL; j++) {
                float ev = ebv[j] + r[u].y * ew0[j] + r[u].z * ew1[j] + r[u].w * ew2[j];
                acc[j] += fmaxf(xv[u][j] + ev, 0.f);
            }
    }
    for (; p < end; p++) {
        float4 r0 = __ldg(&recs[p]);
        int xoff = __float_as_int(r0.x) * CH + c0;
        float x0[VPL];
        *(float2*)x0 = *(const float2*)&x[xoff];
#pragma unroll
        for (int j = 0; j < VPL; j++) {
            float e0 = ebv[j] + r0.y * ew0[j] + r0.z * ew1[j] + r0.w * ew2[j];
            acc[j] += fmaxf(x0[j] + e0, 0.f);
        }
    }
    int soff = node * CH + c0;
    float sv[VPL];
    *(float2*)sv = *(const float2*)&x[soff];
#pragma unroll
    for (int j = 0; j < VPL; j++) sv[j] += acc[j];
    *(float2*)&out[soff] = *(float2*)sv;
}

// ---------------- fused 2-GEMM node MLP (unchanged, proven) ----------------
template <int K1>
__global__ __launch_bounds__(256, 2) void fused_mlp_kernel(
    const float* __restrict__ A, const float* __restrict__ W1, const float* __restrict__ b1,
    const float* __restrict__ W2, const float* __restrict__ b2, float* __restrict__ C) {
    extern __shared__ uint32_t sm[];
    uint32_t (*As)[20]   = (uint32_t(*)[20])sm;
    uint32_t (*Ws)[136]  = (uint32_t(*)[136])(sm + 128 * 20);
    uint32_t (*Mid)[132] = (uint32_t(*)[132])(sm + 128 * 20 + 16 * 136);

    const int tid = threadIdx.x, lane = tid & 31, wid = tid >> 5;
    const int block_row = blockIdx.x * 128;
    const int rbase = (wid & 3) * 32;
    const int cbase = (wid >> 2) * 64;
    const int g4 = lane >> 2;
    const int t4 = lane & 3;

    float acc[2][8][4];
#pragma unroll
    for (int i = 0; i < 2; i++)
#pragma unroll
        for (int j = 0; j < 8; j++)
#pragma unroll
            for (int q = 0; q < 4; q++) acc[i][j][q] = 0.f;

    for (int k0 = 0; k0 < K1; k0 += 16) {
#pragma unroll
        for (int i = 0; i < 2; i++) {
            int idx = tid + i * 256;
            int r = idx >> 2;
            int kc = (idx & 3) * 4;
            int gr = block_row + r;
            float4 v = make_float4(0.f, 0.f, 0.f, 0.f);
            if (gr < NN) v = *(const float4*)&A[(long long)gr * K1 + k0 + kc];
            *(uint4*)&As[r][kc] = make_uint4(f2tf32(v.x), f2tf32(v.y), f2tf32(v.z), f2tf32(v.w));
        }
#pragma unroll
        for (int i = 0; i < 2; i++) {
            int idx = tid + i * 256;
            int r = idx >> 5;
            int cc = (idx & 31) * 4;
            float4 v = *(const float4*)&W1[(long long)(k0 + r) * 128 + cc];
            *(uint4*)&Ws[r][cc] = make_uint4(f2tf32(v.x), f2tf32(v.y), f2tf32(v.z), f2tf32(v.w));
        }
        __syncthreads();
#pragma unroll
        for (int ks = 0; ks < 2; ks++) {
            const int kk = ks * 8;
            uint32_t a[2][4];
#pragma unroll
            for (int i = 0; i < 2; i++) {
                int r = rbase + i * 16 + g4;
                a[i][0] = As[r][kk + t4];
                a[i][1] = As[r + 8][kk + t4];
                a[i][2] = As[r][kk + t4 + 4];
                a[i][3] = As[r + 8][kk + t4 + 4];
            }
#pragma unroll
            for (int j = 0; j < 8; j++) {
                int cn = cbase + j * 8 + g4;
                uint32_t b0 = Ws[kk + t4][cn];
                uint32_t b1 = Ws[kk + t4 + 4][cn];
#pragma unroll
                for (int i = 0; i < 2; i++) mma16n8k8(acc[i][j], a[i], b0, b1);
            }
        }
        __syncthreads();
    }
#pragma unroll
    for (int j = 0; j < 8; j++) {
        int col = cbase + j * 8 + t4 * 2;
        float bx = __ldg(&b1[col]);
        float by = __ldg(&b1[col + 1]);
#pragma unroll
        for (int i = 0; i < 2; i++) {
            int r0 = rbase + i * 16 + g4;
            Mid[r0][col]         = f2tf32(fmaxf(acc[i][j][0] + bx, 0.f));
            Mid[r0][col + 1]     = f2tf32(fmaxf(acc[i][j][1] + by, 0.f));
            Mid[r0 + 8][col]     = f2tf32(fmaxf(acc[i][j][2] + bx, 0.f));
            Mid[r0 + 8][col + 1] = f2tf32(fmaxf(acc[i][j][3] + by, 0.f));
            acc[i][j][0] = 0.f; acc[i][j][1] = 0.f; acc[i][j][2] = 0.f; acc[i][j][3] = 0.f;
        }
    }
    __syncthreads();

    for (int k0 = 0; k0 < 128; k0 += 16) {
#pragma unroll
        for (int i = 0; i < 2; i++) {
            int idx = tid + i * 256;
            int r = idx >> 5;
            int cc = (idx & 31) * 4;
            float4 v = *(const float4*)&W2[(long long)(k0 + r) * 128 + cc];
            *(uint4*)&Ws[r][cc] = make_uint4(f2tf32(v.x), f2tf32(v.y), f2tf32(v.z), f2tf32(v.w));
        }
        __syncthreads();
#pragma unroll
        for (int ks = 0; ks < 2; ks++) {
            const int kk = ks * 8;
            uint32_t a[2][4];
#pragma unroll
            for (int i = 0; i < 2; i++) {
                int r = rbase + i * 16 + g4;
                a[i][0] = Mid[r][k0 + kk + t4];
                a[i][1] = Mid[r + 8][k0 + kk + t4];
                a[i][2] = Mid[r][k0 + kk + t4 + 4];
                a[i][3] = Mid[r + 8][k0 + kk + t4 + 4];
            }
#pragma unroll
            for (int j = 0; j < 8; j++) {
                int cn = cbase + j * 8 + g4;
                uint32_t b0 = Ws[kk + t4][cn];
                uint32_t b1 = Ws[kk + t4 + 4][cn];
#pragma unroll
                for (int i = 0; i < 2; i++) mma16n8k8(acc[i][j], a[i], b0, b1);
            }
        }
        __syncthreads();
    }
#pragma unroll
    for (int j = 0; j < 8; j++) {
        int col = cbase + j * 8 + t4 * 2;
        float bx = __ldg(&b2[col]);
        float by = __ldg(&b2[col + 1]);
#pragma unroll
        for (int i = 0; i < 2; i++) {
            int r0 = block_row + rbase + i * 16 + g4;
            if (r0 < NN) {
                float2 o0 = make_float2(fmaxf(acc[i][j][0] + bx, 0.f),
                                        fmaxf(acc[i][j][1] + by, 0.f));
                *(float2*)&C[(long long)r0 * 128 + col] = o0;
            }
            if (r0 + 8 < NN) {
                float2 o1 = make_float2(fmaxf(acc[i][j][2] + bx, 0.f),
                                        fmaxf(acc[i][j][3] + by, 0.f));
                *(float2*)&C[(long long)(r0 + 8) * 128 + col] = o1;
            }
        }
    }
}

// ---------------- global mean pool ----------------
__global__ void pool_kernel(const float* __restrict__ h, const void* __restrict__ batch,
                            float* __restrict__ pool, float* __restrict__ cnt) {
    int idx = blockIdx.x * blockDim.x + threadIdx.x;   // 32-bit: NN*32 = 1.6M
    if (idx >= NN * 32) return;
    int n = idx >> 5;
    int c4 = (idx & 31) * 4;
    int g = (int)load_idx(batch, n, g_is64);
    float4 v = *(const float4*)&h[n * 128 + c4];
    red_add_v4(&pool[g * 128 + c4], v.x, v.y, v.z, v.w);
    if (c4 == 0) atomicAdd(&cnt[g], 1.0f);
}
__global__ void finalize_kernel(const float* __restrict__ pool, const float* __restrict__ cnt,
                                float* __restrict__ out) {
    int i = blockIdx.x * blockDim.x + threadIdx.x;
    if (i < NG * 128) out[i] = pool[i] / fmaxf(cnt[i >> 7], 1.0f);
}

// ---------------- launch ----------------
extern "C" void kernel_launch(void* const* d_in, const int* in_sizes, int n_in,
                              void* d_out, int out_size) {
    const float* x     = (const float*)d_in[0];
    const void*  ei    = d_in[1];
    const float* attr  = (const float*)d_in[2];
    const void*  batch = d_in[3];
    const float* el1_w = (const float*)d_in[4];
    const float* el1_b = (const float*)d_in[5];
    const float* w1a   = (const float*)d_in[6];
    const float* b1a   = (const float*)d_in[7];
    const float* w1b   = (const float*)d_in[8];
    const float* b1b   = (const float*)d_in[9];
    const float* el2_w = (const float*)d_in[10];
    const float* el2_b = (const float*)d_in[11];
    const float* w2a   = (const float*)d_in[12];
    const float* b2a   = (const float*)d_in[13];
    const float* w2b   = (const float*)d_in[14];
    const float* b2b   = (const float*)d_in[15];
    float* out = (float*)d_out;

    float *agg, *h, *pool, *cnt;
    int *cntE, *rowptr, *wofs, *bsum;
    float4* erec;
    cudaGetSymbolAddress((void**)&agg,  g_agg);
    cudaGetSymbolAddress((void**)&h,    g_h);
    cudaGetSymbolAddress((void**)&pool, g_pool);
    cudaGetSymbolAddress((void**)&cnt,  g_cnt);
    cudaGetSymbolAddress((void**)&cntE,   g_cntE);
    cudaGetSymbolAddress((void**)&rowptr, g_rowptr);
    cudaGetSymbolAddress((void**)&wofs,   g_wofs);
    cudaGetSymbolAddress((void**)&erec,   g_erec);
    cudaGetSymbolAddress((void**)&bsum,   g_bsum);

    const int SMF = (128 * 20 + 16 * 136 + 128 * 132) * 4;   // 86528 B
    cudaFuncSetAttribute(fused_mlp_kernel<64>,  cudaFuncAttributeMaxDynamicSharedMemorySize, SMF);
    cudaFuncSetAttribute(fused_mlp_kernel<128>, cudaFuncAttributeMaxDynamicSharedMemorySize, SMF);

    // 1: init (detect + all zeroing)
    init_kernel<<<59, 256>>>((const int*)ei);

    // 2-5: CSR build (scan2 folded into scan3)
    const int NB = (NN + 511) / 512;   // 98
    hist_kernel<<<(NE + 255) / 256, 256>>>(ei, cntE);
    scan1_kernel<<<NB, 512>>>(cntE, rowptr, bsum);
    scan3_kernel<<<NB, 512>>>(rowptr, bsum, wofs);
    scatter_kernel<<<(NE + 255) / 256, 256>>>(ei, attr, wofs, erec);

    const int ggrid = (NN + 127) / 128;

    // 6-7: layer 1 (SPLIT=1: 50k warps, VPL=2)
    {
        long long t = (long long)NN * 32;
        agg_kernel<64, 1><<<(int)((t + 255) / 256), 256>>>(x, erec, el1_w, el1_b, rowptr, agg);
    }
    fused_mlp_kernel<64><<<ggrid, 256, SMF>>>(agg, w1a, b1a, w1b, b1b, h);

    // 8-9: layer 2 (SPLIT=2: 100k half-warps, VPL=2)
    {
        long long t = (long long)NN * 64;
        agg_kernel<128, 2><<<(int)((t + 255) / 256), 256>>>(h, erec, el2_w, el2_b, rowptr, agg);
    }
    fused_mlp_kernel<128><<<ggrid, 256, SMF>>>(agg, w2a, b2a, w2b, b2b, h);

    // 10-11: pool + finalize
    {
        long long t = (long long)NN * 32;
        pool_kernel<<<(int)((t + 255) / 256), 256>>>(h, batch, pool, cnt);
    }
    finalize_kernel<<<(NG * 128 + 255) / 256, 256>>>(pool, cnt, out);
}